// round 15
// baseline (speedup 1.0000x reference)
#include <cuda_runtime.h>
#include <cuda_fp16.h>
#include <stdint.h>
#include <math.h>

// ---------------------------------------------------------------------------
// GCLSTM (K=1 ChebConv -> edge data unused). fp16 HMMA path.
//   pack(Wt,bias) -> GEMM1 -> fused[gates+GEMM2]      [default stream]
//   pack(WlinT)  || GEMM1                             [side stream]
//   GEMM1: P(fp16) = [x|h](fp32, cvt in-loader) @ Wt^T + bias (50000x1024x512)
//   fused: per K-chunk, gates computed from smem-staged P/c; writes h0,c0
//          (fp32, global) and R=relu(h0) fp16 directly into the A tile;
//          out = R @ WlinT^T + b_lin.
// Output tuple: [out | h0 | c0], each 50000*256 fp32.
// ---------------------------------------------------------------------------

#define NNODES 50000

__device__ __half g_P[(size_t)NNODES * 1024];
__device__ __half g_Wt[1024 * 512];
__device__ __half g_WlT[256 * 256];
__device__ float  g_bias[1024];

// ---------------------------------------------------------------------------
__device__ __forceinline__ uint32_t smem_u32(const void* p) {
    uint32_t a;
    asm("{ .reg .u64 t; cvta.to.shared.u64 t, %1; cvt.u32.u64 %0, t; }"
        : "=r"(a) : "l"(p));
    return a;
}
__device__ __forceinline__ void ldm4(uint32_t* a, uint32_t addr) {
    asm volatile("ldmatrix.sync.aligned.m8n8.x4.shared.b16 {%0,%1,%2,%3}, [%4];"
        : "=r"(a[0]), "=r"(a[1]), "=r"(a[2]), "=r"(a[3]) : "r"(addr));
}
__device__ __forceinline__ void mma16816(float* d, const uint32_t* a, const uint32_t* b) {
    asm volatile(
        "mma.sync.aligned.m16n8k16.row.col.f32.f16.f16.f32 "
        "{%0,%1,%2,%3},{%4,%5,%6,%7},{%8,%9},{%0,%1,%2,%3};"
        : "+f"(d[0]), "+f"(d[1]), "+f"(d[2]), "+f"(d[3])
        : "r"(a[0]), "r"(a[1]), "r"(a[2]), "r"(a[3]), "r"(b[0]), "r"(b[1]));
}
__device__ __forceinline__ void cp16(uint32_t dst, const void* src) {
    asm volatile("cp.async.cg.shared.global [%0], [%1], 16;" :: "r"(dst), "l"(src));
}
__device__ __forceinline__ void cp_commit() { asm volatile("cp.async.commit_group;"); }
template <int N>
__device__ __forceinline__ void cp_wait() {
    asm volatile("cp.async.wait_group %0;" :: "n"(N));
}

__device__ __forceinline__ float sigf(float x)  { return 1.f / (1.f + __expf(-x)); }
__device__ __forceinline__ float tanf_(float x) { return 2.f / (1.f + __expf(-2.f * x)) - 1.f; }

// ---------------------------------------------------------------------------
// GEMM1: BM=128, BN=256, BK=32, 8 warps (2m x 4n), warp 64x64, 4-stage.
// A = [x|h] fp32 converted in-loader; B fp16 cp.async; P(fp16) = A@B^T + bias.
// (R11 kernel, unchanged — best measured.)
// ---------------------------------------------------------------------------
#define ABUF1 (128 * 80)
#define BBUF1 (256 * 80)
#define STG1  (ABUF1 + BBUF1)
#define SMEM1 (4 * STG1)             // 122880

__global__ void __launch_bounds__(256, 1)
gemm1_kernel(const float* __restrict__ Ax, const float* __restrict__ Ah,
             const __half* __restrict__ B, __half* __restrict__ C,
             const float* __restrict__ bias, int M)
{
    extern __shared__ __align__(16) char usm[];
    __shared__ float sbias[256];

    const int tid  = threadIdx.x;
    const int lane = tid & 31;
    const int wid  = tid >> 5;
    const int warpm = wid >> 2;
    const int warpn = wid & 3;
    const int m0 = blockIdx.y * 128;
    const int n0 = blockIdx.x * 256;
    const int K = 512, Ntot = 1024;

    const uint32_t smb = smem_u32(usm);
    sbias[tid] = bias[n0 + tid];

    float acc[4][8][4];
#pragma unroll
    for (int mt = 0; mt < 4; ++mt)
#pragma unroll
        for (int nt = 0; nt < 8; ++nt)
#pragma unroll
            for (int e = 0; e < 4; ++e) acc[mt][nt][e] = 0.f;

    float4 areg[4];
    const int a_r  = tid >> 3;
    const int a_fq = tid & 7;

    auto fetchA32 = [&](int kc) {
        const float* src = (kc < 8) ? Ax : Ah;
        const int cb = (kc & 7) * 32;
#pragma unroll
        for (int q = 0; q < 4; ++q) {
            int r = a_r + q * 32;
            int gr = m0 + r;
            areg[q] = make_float4(0.f, 0.f, 0.f, 0.f);
            if (gr < M)
                areg[q] = *(const float4*)(src + (size_t)gr * 256 + cb + a_fq * 4);
        }
    };
    auto storeA32 = [&](int st) {
#pragma unroll
        for (int q = 0; q < 4; ++q) {
            int r = a_r + q * 32;
            __half2 h0 = __floats2half2_rn(areg[q].x, areg[q].y);
            __half2 h1 = __floats2half2_rn(areg[q].z, areg[q].w);
            uint2 v;
            v.x = *(uint32_t*)&h0;
            v.y = *(uint32_t*)&h1;
            *(uint2*)(usm + st * STG1 + r * 80 + a_fq * 8) = v;
        }
    };
    auto issueB = [&](int kc, int st) {
        const uint32_t bb = smb + st * STG1 + ABUF1;
#pragma unroll
        for (int q = 0; q < 4; ++q) {
            int u = tid + q * 256;
            int r = u >> 2, kq = u & 3;
            cp16(bb + r * 80 + kq * 16,
                 B + (size_t)(n0 + r) * K + kc * 32 + kq * 8);
        }
    };

    fetchA32(0); storeA32(0);
    fetchA32(1); storeA32(1);
    fetchA32(2); storeA32(2);
    issueB(0, 0); cp_commit();
    issueB(1, 1); cp_commit();
    issueB(2, 2); cp_commit();
    cp_wait<2>();
    __syncthreads();

    const int arow = warpm * 64 + (lane & 15);
    const int aoff = (lane >> 4) * 8;
    const int brow = warpn * 64 + ((lane >> 4) << 3) + (lane & 7);
    const int boff = ((lane >> 3) & 1) * 8;

    const int nch = K >> 5;
    for (int t = 0; t < nch; ++t) {
        const bool pf = (t + 3 < nch);
        if (pf) {
            fetchA32(t + 3);
            issueB(t + 3, (t + 3) & 3);
        }
        cp_commit();

        const int st = t & 3;
        const uint32_t ab = smb + st * STG1 + arow * 80;
        const uint32_t bb = smb + st * STG1 + ABUF1 + brow * 80;
#pragma unroll
        for (int ks = 0; ks < 2; ++ks) {
            const int k0 = ks * 16;
            uint32_t afr[4][4], bfr[8][2];
#pragma unroll
            for (int mt = 0; mt < 4; ++mt)
                ldm4(afr[mt], ab + mt * 16 * 80 + (k0 + aoff) * 2);
#pragma unroll
            for (int np = 0; np < 4; ++np) {
                uint32_t f[4];
                ldm4(f, bb + np * 16 * 80 + (k0 + boff) * 2);
                bfr[np * 2][0] = f[0]; bfr[np * 2][1] = f[1];
                bfr[np * 2 + 1][0] = f[2]; bfr[np * 2 + 1][1] = f[3];
            }
#pragma unroll
            for (int mt = 0; mt < 4; ++mt)
#pragma unroll
                for (int nt = 0; nt < 8; ++nt)
                    mma16816(acc[mt][nt], afr[mt], bfr[nt]);
        }

        if (pf) storeA32((t + 3) & 3);
        cp_wait<2>();
        __syncthreads();
    }

#pragma unroll
    for (int mt = 0; mt < 4; ++mt) {
        int r0 = m0 + warpm * 64 + mt * 16 + (lane >> 2);
        int r1 = r0 + 8;
#pragma unroll
        for (int nt = 0; nt < 8; ++nt) {
            int cl = warpn * 64 + nt * 8 + (lane & 3) * 2;
            int cg = n0 + cl;
            float b0 = sbias[cl], b1 = sbias[cl + 1];
            if (r0 < M)
                *(__half2*)(C + (size_t)r0 * Ntot + cg) =
                    __floats2half2_rn(acc[mt][nt][0] + b0, acc[mt][nt][1] + b1);
            if (r1 < M)
                *(__half2*)(C + (size_t)r1 * Ntot + cg) =
                    __floats2half2_rn(acc[mt][nt][2] + b0, acc[mt][nt][3] + b1);
        }
    }
}

// ---------------------------------------------------------------------------
// Fused gates + GEMM2. BM=128, BN=256, grid (1, ceil(M/128)), 256 threads,
// warp tile 64x64. K=256 (hidden units), BK=32 -> 8 chunks.
// Per chunk: P-chunk (128x128 halves: 4 gate strips) and c-chunk (128x32 f32)
// cp.async'd into 2-stage scratch; gates computed post-MMA -> h0,c0 (global)
// and R (fp16) STS'd into the 2-stage A tile. B (WlinT) 3-stage cp.async.
// ---------------------------------------------------------------------------
#define AB2   10240                    // A stage: 128*80
#define BB2   20480                    // B stage: 256*80
#define SCRP  (128 * 272)              // 34816 (P: 4*64B strips + 16 pad)
#define SCRC  (128 * 144)              // 18432 (c: 128B + 16 pad)
#define SCR   (SCRP + SCRC)            // 53248
#define OFF_B2   (2 * AB2)             // 20480
#define OFF_SCR  (OFF_B2 + 3 * BB2)    // 81920
#define SMEM2 (OFF_SCR + 2 * SCR)      // 188416

__global__ void __launch_bounds__(256)
gemm2_fused(const __half* __restrict__ P, const float* __restrict__ c_in,
            const __half* __restrict__ B,
            float* __restrict__ out, const float* __restrict__ bias,
            const float* __restrict__ wci, const float* __restrict__ wcf,
            const float* __restrict__ wco,
            float* __restrict__ hout, float* __restrict__ cout, int M)
{
    extern __shared__ __align__(16) char usm[];
    __shared__ float sbias[256];
    __shared__ float swci[256], swcf[256], swco[256];

    const int tid  = threadIdx.x;
    const int lane = tid & 31;
    const int wid  = tid >> 5;
    const int warpm = wid >> 2;
    const int warpn = wid & 3;
    const int m0 = blockIdx.y * 128;
    const int K = 256, Ntot = 256;

    const uint32_t smb = smem_u32(usm);
    sbias[tid] = bias[tid];
    swci[tid] = wci[tid];
    swcf[tid] = wcf[tid];
    swco[tid] = wco[tid];

    float acc[4][8][4];
#pragma unroll
    for (int mt = 0; mt < 4; ++mt)
#pragma unroll
        for (int nt = 0; nt < 8; ++nt)
#pragma unroll
            for (int e = 0; e < 4; ++e) acc[mt][nt][e] = 0.f;

    // ---- cp.async issuers ----
    auto issueB = [&](int kc, int sb) {
        const uint32_t bb = smb + OFF_B2 + sb * BB2;
#pragma unroll
        for (int q = 0; q < 4; ++q) {
            int u = tid + q * 256;
            int r = u >> 2, kq = u & 3;
            cp16(bb + r * 80 + kq * 16,
                 B + (size_t)r * K + kc * 32 + kq * 8);
        }
    };
    auto issueScr = [&](int kc, int s2) {
        const uint32_t sp = smb + OFF_SCR + s2 * SCR;
        // P: 128 rows x 4 gate strips x 64B  -> 2048 cp16 -> 8/thread
#pragma unroll
        for (int q = 0; q < 8; ++q) {
            int u = tid + q * 256;
            int r = u >> 4, rem = u & 15;
            int g = rem >> 2, kq = rem & 3;
            int m = m0 + r;
            if (m < M)
                cp16(sp + r * 272 + g * 64 + kq * 16,
                     P + (size_t)m * 1024 + g * 256 + kc * 32 + kq * 8);
        }
        // c: 128 rows x 128B -> 1024 cp16 -> 4/thread
        const uint32_t sc = sp + SCRP;
#pragma unroll
        for (int q = 0; q < 4; ++q) {
            int u = tid + q * 256;
            int r = u >> 3, kq = u & 7;
            int m = m0 + r;
            if (m < M)
                cp16(sc + r * 144 + kq * 16,
                     c_in + (size_t)m * 256 + kc * 32 + kq * 4);
        }
    };

    // ---- gates build: scratch(kc) -> A tile slot sa + h0/c0 global ----
    const int b_r  = tid >> 1;           // 0..127
    const int b_hf = tid & 1;            // 16-unit half
    auto build = [&](int kc, int sa, int s2) {
        const uint32_t sp = smb + OFF_SCR + s2 * SCR + b_r * 272;
        const uint32_t sc = smb + OFF_SCR + s2 * SCR + SCRP + b_r * 144;
        const uint32_t aw = smb + sa * AB2 + b_r * 80;
        const int m = m0 + b_r;
        const int j0 = kc * 32;
#pragma unroll
        for (int q = 0; q < 4; ++q) {
            int ul = b_hf * 16 + q * 4;          // local unit 0..31
            uint2 pgi = *(uint2*)(usm + (sp - smb) + 0 * 64 + ul * 2);
            uint2 pgf = *(uint2*)(usm + (sp - smb) + 1 * 64 + ul * 2);
            uint2 pgc = *(uint2*)(usm + (sp - smb) + 2 * 64 + ul * 2);
            uint2 pgo = *(uint2*)(usm + (sp - smb) + 3 * 64 + ul * 2);
            float4 cv = *(float4*)(usm + (sc - smb) + ul * 4);
            float pi[4], pf[4], pc[4], po[4];
            { float2 t = __half22float2(*(__half2*)&pgi.x); pi[0]=t.x; pi[1]=t.y; }
            { float2 t = __half22float2(*(__half2*)&pgi.y); pi[2]=t.x; pi[3]=t.y; }
            { float2 t = __half22float2(*(__half2*)&pgf.x); pf[0]=t.x; pf[1]=t.y; }
            { float2 t = __half22float2(*(__half2*)&pgf.y); pf[2]=t.x; pf[3]=t.y; }
            { float2 t = __half22float2(*(__half2*)&pgc.x); pc[0]=t.x; pc[1]=t.y; }
            { float2 t = __half22float2(*(__half2*)&pgc.y); pc[2]=t.x; pc[3]=t.y; }
            { float2 t = __half22float2(*(__half2*)&pgo.x); po[0]=t.x; po[1]=t.y; }
            { float2 t = __half22float2(*(__half2*)&pgo.y); po[2]=t.x; po[3]=t.y; }
            float cva[4] = {cv.x, cv.y, cv.z, cv.w};
            float H[4], Cn[4];
#pragma unroll
            for (int e = 0; e < 4; ++e) {
                int j = j0 + ul + e;
                float I = sigf(pi[e] + swci[j] * cva[e]);
                float F = sigf(pf[e] + swcf[j] * cva[e]);
                float T = tanf_(pc[e]);
                Cn[e] = F * cva[e] + I * T;
                float O = sigf(po[e] + swco[j] * Cn[e]);
                H[e] = O * tanf_(Cn[e]);
            }
            if (m < M) {
                size_t off = (size_t)m * 256 + j0 + ul;
                *(float4*)(hout + off) = make_float4(H[0], H[1], H[2], H[3]);
                *(float4*)(cout + off) = make_float4(Cn[0], Cn[1], Cn[2], Cn[3]);
            }
            __half2 r01 = __floats2half2_rn(fmaxf(H[0], 0.f), fmaxf(H[1], 0.f));
            __half2 r23 = __floats2half2_rn(fmaxf(H[2], 0.f), fmaxf(H[3], 0.f));
            uint2 rv;
            rv.x = *(uint32_t*)&r01;
            rv.y = *(uint32_t*)&r23;
            *(uint2*)(usm + (aw - smb) + ul * 2) = rv;
        }
    };

    // ---- prologue ----
    issueScr(0, 0); issueB(0, 0); cp_commit();
    issueScr(1, 1); issueB(1, 1); cp_commit();
    cp_wait<1>();
    __syncthreads();
    build(0, 0, 0);
    __syncthreads();

    const int arow = warpm * 64 + (lane & 15);
    const int aoff = (lane >> 4) * 8;
    const int brow = warpn * 64 + ((lane >> 4) << 3) + (lane & 7);
    const int boff = ((lane >> 3) & 1) * 8;

    const int nch = K >> 5;   // 8
    for (int t = 0; t < nch; ++t) {
        if (t + 2 < nch) { issueScr(t + 2, (t + 2) & 1); issueB(t + 2, (t + 2) % 3); }
        cp_commit();

        const uint32_t ab = smb + (t & 1) * AB2 + arow * 80;
        const uint32_t bb = smb + OFF_B2 + (t % 3) * BB2 + brow * 80;
#pragma unroll
        for (int ks = 0; ks < 2; ++ks) {
            const int k0 = ks * 16;
            uint32_t afr[4][4], bfr[8][2];
#pragma unroll
            for (int mt = 0; mt < 4; ++mt)
                ldm4(afr[mt], ab + mt * 16 * 80 + (k0 + aoff) * 2);
#pragma unroll
            for (int np = 0; np < 4; ++np) {
                uint32_t f[4];
                ldm4(f, bb + np * 16 * 80 + (k0 + boff) * 2);
                bfr[np * 2][0] = f[0]; bfr[np * 2][1] = f[1];
                bfr[np * 2 + 1][0] = f[2]; bfr[np * 2 + 1][1] = f[3];
            }
#pragma unroll
            for (int mt = 0; mt < 4; ++mt)
#pragma unroll
                for (int nt = 0; nt < 8; ++nt)
                    mma16816(acc[mt][nt], afr[mt], bfr[nt]);
        }

        cp_wait<1>();
        __syncthreads();
        if (t + 1 < nch) build(t + 1, (t + 1) & 1, (t + 1) & 1);
        __syncthreads();
    }

    // ---- epilogue ----
#pragma unroll
    for (int mt = 0; mt < 4; ++mt) {
        int r0 = m0 + warpm * 64 + mt * 16 + (lane >> 2);
        int r1 = r0 + 8;
#pragma unroll
        for (int nt = 0; nt < 8; ++nt) {
            int cl = warpn * 64 + nt * 8 + (lane & 3) * 2;
            float b0 = sbias[cl], b1 = sbias[cl + 1];
            if (r0 < M)
                *(float2*)(out + (size_t)r0 * Ntot + cl) =
                    make_float2(acc[mt][nt][0] + b0, acc[mt][nt][1] + b1);
            if (r1 < M)
                *(float2*)(out + (size_t)r1 * Ntot + cl) =
                    make_float2(acc[mt][nt][2] + b0, acc[mt][nt][3] + b1);
        }
    }
}

// ---------------------------------------------------------------------------
__global__ void pack_main(
    const float* __restrict__ Wi, const float* __restrict__ Wf,
    const float* __restrict__ Wc, const float* __restrict__ Wo,
    const float* __restrict__ Ti, const float* __restrict__ Tf,
    const float* __restrict__ Tc, const float* __restrict__ To,
    const float* __restrict__ bthi, const float* __restrict__ bthf,
    const float* __restrict__ bthc, const float* __restrict__ btho,
    const float* __restrict__ bi, const float* __restrict__ bf,
    const float* __restrict__ bc, const float* __restrict__ bo)
{
    int idx = blockIdx.x * blockDim.x + threadIdx.x;
    if (idx < 524288) {
        int n = idx >> 9, k = idx & 511;
        int g = n >> 8, jj = n & 255;
        float v;
        if (k < 256) {
            const float* W = (g == 0) ? Wi : (g == 1) ? Wf : (g == 2) ? Wc : Wo;
            v = W[k * 256 + jj];
        } else {
            const float* T = (g == 0) ? Ti : (g == 1) ? Tf : (g == 2) ? Tc : To;
            v = T[(k - 256) * 256 + jj];
        }
        g_Wt[idx] = __float2half_rn(v);
    } else if (idx < 524288 + 1024) {
        int j = idx - 524288;
        int g = j >> 8, jj = j & 255;
        const float* bth = (g == 0) ? bthi : (g == 1) ? bthf : (g == 2) ? bthc : btho;
        const float* bb  = (g == 0) ? bi   : (g == 1) ? bf   : (g == 2) ? bc   : bo;
        g_bias[j] = bth[jj] + bb[jj];
    }
}

__global__ void pack_wlin(const float* __restrict__ Wlin)
{
    int idx = blockIdx.x * blockDim.x + threadIdx.x;
    if (idx < 65536) {
        int n = idx >> 8, k = idx & 255;
        g_WlT[idx] = __float2half_rn(Wlin[k * 256 + n]);
    }
}

// ---------------------------------------------------------------------------
extern "C" void kernel_launch(void* const* d_in, const int* in_sizes, int n_in,
                              void* d_out, int out_size)
{
    const float* x    = (const float*)d_in[0];
    // d_in[1] edge_index, d_in[2] edge_weight -> unused (K=1 ChebConv)
    const float* h    = (const float*)d_in[3];
    const float* c    = (const float*)d_in[4];
    const float* Wi   = (const float*)d_in[5];
    const float* Wf   = (const float*)d_in[6];
    const float* Wc   = (const float*)d_in[7];
    const float* Wo   = (const float*)d_in[8];
    const float* Ti   = (const float*)d_in[9];
    const float* Tf   = (const float*)d_in[10];
    const float* Tc   = (const float*)d_in[11];
    const float* To   = (const float*)d_in[12];
    const float* bthi = (const float*)d_in[13];
    const float* bthf = (const float*)d_in[14];
    const float* bthc = (const float*)d_in[15];
    const float* btho = (const float*)d_in[16];
    const float* wci  = (const float*)d_in[17];
    const float* wcf  = (const float*)d_in[18];
    const float* wco  = (const float*)d_in[19];
    const float* bi   = (const float*)d_in[20];
    const float* bf   = (const float*)d_in[21];
    const float* bc   = (const float*)d_in[22];
    const float* bo   = (const float*)d_in[23];
    const float* Wlin = (const float*)d_in[24];
    const float* blin = (const float*)d_in[25];
    float* out = (float*)d_out;

    float *pBias;
    __half *pP, *pWt, *pWlT;
    cudaGetSymbolAddress((void**)&pBias, g_bias);
    cudaGetSymbolAddress((void**)&pP, g_P);
    cudaGetSymbolAddress((void**)&pWt, g_Wt);
    cudaGetSymbolAddress((void**)&pWlT, g_WlT);

    cudaFuncSetAttribute(gemm1_kernel,
                         cudaFuncAttributeMaxDynamicSharedMemorySize, SMEM1);
    cudaFuncSetAttribute(gemm2_fused,
                         cudaFuncAttributeMaxDynamicSharedMemorySize, SMEM2);

    // one-time host-side stream/event setup (no device memory)
    static cudaStream_t s2 = nullptr;
    static cudaEvent_t evFork, evWlin;
    if (!s2) {
        cudaStreamCreateWithFlags(&s2, cudaStreamNonBlocking);
        cudaEventCreateWithFlags(&evFork, cudaEventDisableTiming);
        cudaEventCreateWithFlags(&evWlin, cudaEventDisableTiming);
    }

    const size_t elems = (size_t)NNODES * 256;
    float* hout = out + elems;
    float* cout = out + 2 * elems;

    // pack Wt+bias (default; GEMM1 depends on it)
    pack_main<<<(524288 + 1024 + 255) / 256, 256>>>(
        Wi, Wf, Wc, Wo, Ti, Tf, Tc, To,
        bthi, bthf, bthc, btho, bi, bf, bc, bo);

    // pack WlinT on side stream (overlaps GEMM1)
    cudaEventRecord(evFork, 0);
    cudaStreamWaitEvent(s2, evFork, 0);
    pack_wlin<<<65536 / 256, 256, 0, s2>>>(Wlin);
    cudaEventRecord(evWlin, s2);

    // GEMM1: P = [x|h] @ Wt^T + bias
    gemm1_kernel<<<dim3(4, (NNODES + 127) / 128), 256, SMEM1>>>(
        x, h, pWt, pP, pBias, NNODES);

    // fused gates + GEMM2
    cudaStreamWaitEvent(0, evWlin, 0);
    gemm2_fused<<<dim3(1, (NNODES + 127) / 128), 256, SMEM2>>>(
        pP, c, pWlT, out, blin, wci, wcf, wco, hout, cout, NNODES);
}

// round 16
// speedup vs baseline: 1.4084x; 1.4084x over previous
#include <cuda_runtime.h>
#include <cuda_fp16.h>
#include <stdint.h>
#include <math.h>

// ---------------------------------------------------------------------------
// GCLSTM (K=1 ChebConv -> edge data unused). fp16 HMMA path (best composition):
//   pack(Wt,bias) -> GEMM1 -> gates -> GEMM2      [default stream]
//   pack(WlinT)  || GEMM1                          [side stream]
//   GEMM1: P(fp16) = [x|h](fp32, cvt in-loader) @ Wt^T + bias (50000x1024x512)
//   gates: h0, c0 (fp32), R = relu(h0) (fp16)
//   GEMM2: out = R @ WlinT^T + b_lin  (50000x256x256)
// GEMM: BM=128, BN=256, BK=32, 8 warps (2m x 4n), warp 64x64, 4-stage cp.async.
// Output tuple: [out | h0 | c0], each 50000*256 fp32.
// ---------------------------------------------------------------------------

#define NNODES 50000

__device__ __half g_P[(size_t)NNODES * 1024];
__device__ __half g_R[(size_t)NNODES * 256];
__device__ __half g_Wt[1024 * 512];
__device__ __half g_WlT[256 * 256];
__device__ float  g_bias[1024];

// ---------------------------------------------------------------------------
__device__ __forceinline__ uint32_t smem_u32(const void* p) {
    uint32_t a;
    asm("{ .reg .u64 t; cvta.to.shared.u64 t, %1; cvt.u32.u64 %0, t; }"
        : "=r"(a) : "l"(p));
    return a;
}
__device__ __forceinline__ void ldm4(uint32_t* a, uint32_t addr) {
    asm volatile("ldmatrix.sync.aligned.m8n8.x4.shared.b16 {%0,%1,%2,%3}, [%4];"
        : "=r"(a[0]), "=r"(a[1]), "=r"(a[2]), "=r"(a[3]) : "r"(addr));
}
__device__ __forceinline__ void mma16816(float* d, const uint32_t* a, const uint32_t* b) {
    asm volatile(
        "mma.sync.aligned.m16n8k16.row.col.f32.f16.f16.f32 "
        "{%0,%1,%2,%3},{%4,%5,%6,%7},{%8,%9},{%0,%1,%2,%3};"
        : "+f"(d[0]), "+f"(d[1]), "+f"(d[2]), "+f"(d[3])
        : "r"(a[0]), "r"(a[1]), "r"(a[2]), "r"(a[3]), "r"(b[0]), "r"(b[1]));
}
__device__ __forceinline__ void cp16(uint32_t dst, const void* src) {
    asm volatile("cp.async.cg.shared.global [%0], [%1], 16;" :: "r"(dst), "l"(src));
}
__device__ __forceinline__ void cp_commit() { asm volatile("cp.async.commit_group;"); }
template <int N>
__device__ __forceinline__ void cp_wait() {
    asm volatile("cp.async.wait_group %0;" :: "n"(N));
}

__device__ __forceinline__ float sigf(float x)  { return 1.f / (1.f + __expf(-x)); }
__device__ __forceinline__ float tanf_(float x) { return 2.f / (1.f + __expf(-2.f * x)) - 1.f; }

// ---------------------------------------------------------------------------
// HMMA GEMM: BM=128, BN=256, BK=32, 8 warps (2m x 4n), warp tile 64x64,
// 4-stage. B via cp.async.
// G1=true : A = [x|h] fp32, LDG->cvt->STS loader; C fp16 (P).
// G1=false: A fp16 via cp.async; C fp32.
// ---------------------------------------------------------------------------
#define ABUF (128 * 80)
#define BBUF (256 * 80)
#define STG  (ABUF + BBUF)
#define SMEM_DYN (4 * STG)           // 122880 B

template <bool G1>
__global__ void __launch_bounds__(256, 1)
hmma_gemm(const float* __restrict__ Ax, const float* __restrict__ Ah,
          const __half* __restrict__ A16, const __half* __restrict__ B,
          void* __restrict__ Cv, const float* __restrict__ bias,
          int M, int Ntot, int K)
{
    extern __shared__ __align__(16) char usm[];
    __shared__ float sbias[256];

    const int tid  = threadIdx.x;
    const int lane = tid & 31;
    const int wid  = tid >> 5;
    const int warpm = wid >> 2;
    const int warpn = wid & 3;
    const int m0 = blockIdx.y * 128;
    const int n0 = blockIdx.x * 256;

    const uint32_t smb = smem_u32(usm);
    sbias[tid] = bias[n0 + tid];

    float acc[4][8][4];
#pragma unroll
    for (int mt = 0; mt < 4; ++mt)
#pragma unroll
        for (int nt = 0; nt < 8; ++nt)
#pragma unroll
            for (int e = 0; e < 4; ++e) acc[mt][nt][e] = 0.f;

    const int nch = K >> 5;

    // ---- A loaders ----
    float4 areg[4];
    const int a_r  = tid >> 3;
    const int a_fq = tid & 7;

    auto fetchA32 = [&](int kc) {
        const float* src = (kc < 8) ? Ax : Ah;
        const int cb = (kc & 7) * 32;
#pragma unroll
        for (int q = 0; q < 4; ++q) {
            int r = a_r + q * 32;
            int gr = m0 + r;
            areg[q] = make_float4(0.f, 0.f, 0.f, 0.f);
            if (gr < M)
                areg[q] = *(const float4*)(src + (size_t)gr * 256 + cb + a_fq * 4);
        }
    };
    auto storeA32 = [&](int st) {
#pragma unroll
        for (int q = 0; q < 4; ++q) {
            int r = a_r + q * 32;
            __half2 h0 = __floats2half2_rn(areg[q].x, areg[q].y);
            __half2 h1 = __floats2half2_rn(areg[q].z, areg[q].w);
            uint2 v;
            v.x = *(uint32_t*)&h0;
            v.y = *(uint32_t*)&h1;
            *(uint2*)(usm + st * STG + r * 80 + a_fq * 8) = v;
        }
    };
    auto issueA16 = [&](int kc, int st) {
#pragma unroll
        for (int q = 0; q < 2; ++q) {
            int u = tid + q * 256;
            int r = u >> 2, kq = u & 3;
            int gr = m0 + r;
            if (gr < M)
                cp16(smb + st * STG + r * 80 + kq * 16,
                     A16 + (size_t)gr * K + kc * 32 + kq * 8);
        }
    };
    auto issueB = [&](int kc, int st) {
        const uint32_t bb = smb + st * STG + ABUF;
#pragma unroll
        for (int q = 0; q < 4; ++q) {
            int u = tid + q * 256;
            int r = u >> 2, kq = u & 3;
            cp16(bb + r * 80 + kq * 16,
                 B + (size_t)(n0 + r) * K + kc * 32 + kq * 8);
        }
    };

    // ---- prologue ----
    if (G1) {
        fetchA32(0); storeA32(0);
        fetchA32(1); storeA32(1);
        fetchA32(2); storeA32(2);
        issueB(0, 0); cp_commit();
        issueB(1, 1); cp_commit();
        issueB(2, 2); cp_commit();
    } else {
        issueA16(0, 0); issueB(0, 0); cp_commit();
        issueA16(1, 1); issueB(1, 1); cp_commit();
        issueA16(2, 2); issueB(2, 2); cp_commit();
    }
    cp_wait<2>();
    __syncthreads();

    const int arow = warpm * 64 + (lane & 15);
    const int aoff = (lane >> 4) * 8;
    const int brow = warpn * 64 + ((lane >> 4) << 3) + (lane & 7);
    const int boff = ((lane >> 3) & 1) * 8;

    for (int t = 0; t < nch; ++t) {
        const bool pf = (t + 3 < nch);
        if (pf) {
            if (G1) fetchA32(t + 3);
            else    issueA16(t + 3, (t + 3) & 3);
            issueB(t + 3, (t + 3) & 3);
        }
        cp_commit();

        const int st = t & 3;
        const uint32_t ab = smb + st * STG + arow * 80;
        const uint32_t bb = smb + st * STG + ABUF + brow * 80;
#pragma unroll
        for (int ks = 0; ks < 2; ++ks) {
            const int k0 = ks * 16;
            uint32_t afr[4][4], bfr[8][2];
#pragma unroll
            for (int mt = 0; mt < 4; ++mt)
                ldm4(afr[mt], ab + mt * 16 * 80 + (k0 + aoff) * 2);
#pragma unroll
            for (int np = 0; np < 4; ++np) {
                uint32_t f[4];
                ldm4(f, bb + np * 16 * 80 + (k0 + boff) * 2);
                bfr[np * 2][0] = f[0]; bfr[np * 2][1] = f[1];
                bfr[np * 2 + 1][0] = f[2]; bfr[np * 2 + 1][1] = f[3];
            }
#pragma unroll
            for (int mt = 0; mt < 4; ++mt)
#pragma unroll
                for (int nt = 0; nt < 8; ++nt)
                    mma16816(acc[mt][nt], afr[mt], bfr[nt]);
        }

        if (G1 && pf) storeA32((t + 3) & 3);
        cp_wait<2>();
        __syncthreads();
    }

    // ---- epilogue ----
#pragma unroll
    for (int mt = 0; mt < 4; ++mt) {
        int r0 = m0 + warpm * 64 + mt * 16 + (lane >> 2);
        int r1 = r0 + 8;
#pragma unroll
        for (int nt = 0; nt < 8; ++nt) {
            int cl = warpn * 64 + nt * 8 + (lane & 3) * 2;
            int cg = n0 + cl;
            float b0 = sbias[cl], b1 = sbias[cl + 1];
            if (G1) {
                __half* C = (__half*)Cv;
                if (r0 < M)
                    *(__half2*)(C + (size_t)r0 * Ntot + cg) =
                        __floats2half2_rn(acc[mt][nt][0] + b0, acc[mt][nt][1] + b1);
                if (r1 < M)
                    *(__half2*)(C + (size_t)r1 * Ntot + cg) =
                        __floats2half2_rn(acc[mt][nt][2] + b0, acc[mt][nt][3] + b1);
            } else {
                float* C = (float*)Cv;
                if (r0 < M)
                    *(float2*)(C + (size_t)r0 * Ntot + cg) =
                        make_float2(acc[mt][nt][0] + b0, acc[mt][nt][1] + b1);
                if (r1 < M)
                    *(float2*)(C + (size_t)r1 * Ntot + cg) =
                        make_float2(acc[mt][nt][2] + b0, acc[mt][nt][3] + b1);
            }
        }
    }
}

// ---------------------------------------------------------------------------
// pack_main: g_Wt[n][k] = Wall[k][n] fp16, g_bias = bth + b. (GEMM1 dep)
// ---------------------------------------------------------------------------
__global__ void pack_main(
    const float* __restrict__ Wi, const float* __restrict__ Wf,
    const float* __restrict__ Wc, const float* __restrict__ Wo,
    const float* __restrict__ Ti, const float* __restrict__ Tf,
    const float* __restrict__ Tc, const float* __restrict__ To,
    const float* __restrict__ bthi, const float* __restrict__ bthf,
    const float* __restrict__ bthc, const float* __restrict__ btho,
    const float* __restrict__ bi, const float* __restrict__ bf,
    const float* __restrict__ bc, const float* __restrict__ bo)
{
    int idx = blockIdx.x * blockDim.x + threadIdx.x;
    if (idx < 524288) {
        int n = idx >> 9, k = idx & 511;
        int g = n >> 8, jj = n & 255;
        float v;
        if (k < 256) {
            const float* W = (g == 0) ? Wi : (g == 1) ? Wf : (g == 2) ? Wc : Wo;
            v = W[k * 256 + jj];
        } else {
            const float* T = (g == 0) ? Ti : (g == 1) ? Tf : (g == 2) ? Tc : To;
            v = T[(k - 256) * 256 + jj];
        }
        g_Wt[idx] = __float2half_rn(v);
    } else if (idx < 524288 + 1024) {
        int j = idx - 524288;
        int g = j >> 8, jj = j & 255;
        const float* bth = (g == 0) ? bthi : (g == 1) ? bthf : (g == 2) ? bthc : btho;
        const float* bb  = (g == 0) ? bi   : (g == 1) ? bf   : (g == 2) ? bc   : bo;
        g_bias[j] = bth[jj] + bb[jj];
    }
}

// pack_wlin: g_WlT[n][k] = Wlin[k][n] fp16 (GEMM2 only; runs on side stream)
__global__ void pack_wlin(const float* __restrict__ Wlin)
{
    int idx = blockIdx.x * blockDim.x + threadIdx.x;
    if (idx < 65536) {
        int n = idx >> 8, k = idx & 255;
        g_WlT[idx] = __float2half_rn(Wlin[k * 256 + n]);
    }
}

// ---------------------------------------------------------------------------
// Gates from fp16 P: h0, c0 (fp32) + R (fp16). 8 cols/thread.
// ---------------------------------------------------------------------------
__global__ void gates_kernel(const float* __restrict__ c_in,
                             const float* __restrict__ wci,
                             const float* __restrict__ wcf,
                             const float* __restrict__ wco,
                             float* __restrict__ h_out,
                             float* __restrict__ c_out)
{
    int u = blockIdx.x * blockDim.x + threadIdx.x;   // NNODES*32
    if (u >= NNODES * 32) return;
    int n = u >> 5;
    int j = (u & 31) << 3;
    const __half* P = g_P + (size_t)n * 1024;

    uint4 vi = *(const uint4*)(P + j);
    uint4 vf = *(const uint4*)(P + 256 + j);
    uint4 vc = *(const uint4*)(P + 512 + j);
    uint4 vo = *(const uint4*)(P + 768 + j);
    float4 c0 = *(const float4*)(c_in + (size_t)n * 256 + j);
    float4 c1 = *(const float4*)(c_in + (size_t)n * 256 + j + 4);
    float4 wi0 = *(const float4*)(wci + j), wi1 = *(const float4*)(wci + j + 4);
    float4 wf0 = *(const float4*)(wcf + j), wf1 = *(const float4*)(wcf + j + 4);
    float4 wo0 = *(const float4*)(wco + j), wo1 = *(const float4*)(wco + j + 4);

    float pi[8], pf[8], pc[8], po[8];
    {
        const uint32_t* a = &vi.x;
        const uint32_t* b = &vf.x;
        const uint32_t* cc = &vc.x;
        const uint32_t* d = &vo.x;
#pragma unroll
        for (int q = 0; q < 4; ++q) {
            float2 t;
            t = __half22float2(*(const __half2*)&a[q]);  pi[2*q] = t.x; pi[2*q+1] = t.y;
            t = __half22float2(*(const __half2*)&b[q]);  pf[2*q] = t.x; pf[2*q+1] = t.y;
            t = __half22float2(*(const __half2*)&cc[q]); pc[2*q] = t.x; pc[2*q+1] = t.y;
            t = __half22float2(*(const __half2*)&d[q]);  po[2*q] = t.x; po[2*q+1] = t.y;
        }
    }
    float cv[8]  = {c0.x, c0.y, c0.z, c0.w, c1.x, c1.y, c1.z, c1.w};
    float wia[8] = {wi0.x, wi0.y, wi0.z, wi0.w, wi1.x, wi1.y, wi1.z, wi1.w};
    float wfa[8] = {wf0.x, wf0.y, wf0.z, wf0.w, wf1.x, wf1.y, wf1.z, wf1.w};
    float woa[8] = {wo0.x, wo0.y, wo0.z, wo0.w, wo1.x, wo1.y, wo1.z, wo1.w};

    float H[8], Cn[8];
#pragma unroll
    for (int e = 0; e < 8; ++e) {
        float I = sigf(pi[e] + wia[e] * cv[e]);
        float F = sigf(pf[e] + wfa[e] * cv[e]);
        float T = tanf_(pc[e]);
        Cn[e] = F * cv[e] + I * T;
        float O = sigf(po[e] + woa[e] * Cn[e]);
        H[e] = O * tanf_(Cn[e]);
    }

    size_t off = (size_t)n * 256 + j;
    *(float4*)(h_out + off)     = make_float4(H[0], H[1], H[2], H[3]);
    *(float4*)(h_out + off + 4) = make_float4(H[4], H[5], H[6], H[7]);
    *(float4*)(c_out + off)     = make_float4(Cn[0], Cn[1], Cn[2], Cn[3]);
    *(float4*)(c_out + off + 4) = make_float4(Cn[4], Cn[5], Cn[6], Cn[7]);

    uint4 rv;
    __half2 r01 = __floats2half2_rn(fmaxf(H[0], 0.f), fmaxf(H[1], 0.f));
    __half2 r23 = __floats2half2_rn(fmaxf(H[2], 0.f), fmaxf(H[3], 0.f));
    __half2 r45 = __floats2half2_rn(fmaxf(H[4], 0.f), fmaxf(H[5], 0.f));
    __half2 r67 = __floats2half2_rn(fmaxf(H[6], 0.f), fmaxf(H[7], 0.f));
    rv.x = *(uint32_t*)&r01; rv.y = *(uint32_t*)&r23;
    rv.z = *(uint32_t*)&r45; rv.w = *(uint32_t*)&r67;
    *(uint4*)(g_R + off) = rv;
}

// ---------------------------------------------------------------------------
extern "C" void kernel_launch(void* const* d_in, const int* in_sizes, int n_in,
                              void* d_out, int out_size)
{
    const float* x    = (const float*)d_in[0];
    // d_in[1] edge_index, d_in[2] edge_weight -> unused (K=1 ChebConv)
    const float* h    = (const float*)d_in[3];
    const float* c    = (const float*)d_in[4];
    const float* Wi   = (const float*)d_in[5];
    const float* Wf   = (const float*)d_in[6];
    const float* Wc   = (const float*)d_in[7];
    const float* Wo   = (const float*)d_in[8];
    const float* Ti   = (const float*)d_in[9];
    const float* Tf   = (const float*)d_in[10];
    const float* Tc   = (const float*)d_in[11];
    const float* To   = (const float*)d_in[12];
    const float* bthi = (const float*)d_in[13];
    const float* bthf = (const float*)d_in[14];
    const float* bthc = (const float*)d_in[15];
    const float* btho = (const float*)d_in[16];
    const float* wci  = (const float*)d_in[17];
    const float* wcf  = (const float*)d_in[18];
    const float* wco  = (const float*)d_in[19];
    const float* bi   = (const float*)d_in[20];
    const float* bf   = (const float*)d_in[21];
    const float* bc   = (const float*)d_in[22];
    const float* bo   = (const float*)d_in[23];
    const float* Wlin = (const float*)d_in[24];
    const float* blin = (const float*)d_in[25];
    float* out = (float*)d_out;

    float *pBias;
    __half *pP, *pWt, *pWlT, *pR;
    cudaGetSymbolAddress((void**)&pBias, g_bias);
    cudaGetSymbolAddress((void**)&pP, g_P);
    cudaGetSymbolAddress((void**)&pWt, g_Wt);
    cudaGetSymbolAddress((void**)&pWlT, g_WlT);
    cudaGetSymbolAddress((void**)&pR, g_R);

    cudaFuncSetAttribute((const void*)hmma_gemm<true>,
                         cudaFuncAttributeMaxDynamicSharedMemorySize, SMEM_DYN);
    cudaFuncSetAttribute((const void*)hmma_gemm<false>,
                         cudaFuncAttributeMaxDynamicSharedMemorySize, SMEM_DYN);

    // one-time host-side stream/event setup (no device memory)
    static cudaStream_t s2 = nullptr;
    static cudaEvent_t evFork, evWlin;
    if (!s2) {
        cudaStreamCreateWithFlags(&s2, cudaStreamNonBlocking);
        cudaEventCreateWithFlags(&evFork, cudaEventDisableTiming);
        cudaEventCreateWithFlags(&evWlin, cudaEventDisableTiming);
    }

    const size_t elems = (size_t)NNODES * 256;
    float* hout = out + elems;
    float* cout = out + 2 * elems;

    // pack Wt+bias (default; GEMM1 depends on it)
    pack_main<<<(524288 + 1024 + 255) / 256, 256>>>(
        Wi, Wf, Wc, Wo, Ti, Tf, Tc, To,
        bthi, bthf, bthc, btho, bi, bf, bc, bo);

    // pack WlinT on side stream (overlaps GEMM1; only GEMM2 needs it)
    cudaEventRecord(evFork, 0);
    cudaStreamWaitEvent(s2, evFork, 0);
    pack_wlin<<<65536 / 256, 256, 0, s2>>>(Wlin);
    cudaEventRecord(evWlin, s2);

    // GEMM1: P = [x|h] @ Wt^T + bias (A converted in-loader)
    hmma_gemm<true><<<dim3(4, (NNODES + 127) / 128), 256, SMEM_DYN>>>(
        x, h, nullptr, pWt, pP, pBias, NNODES, 1024, 512);

    // gates -> h0, c0, R
    gates_kernel<<<(NNODES * 32 + 255) / 256, 256>>>(
        c, wci, wcf, wco, hout, cout);

    // GEMM2: out = R @ WlinT^T + b_lin
    cudaStreamWaitEvent(0, evWlin, 0);
    hmma_gemm<false><<<dim3(1, (NNODES + 127) / 128), 256, SMEM_DYN>>>(
        nullptr, nullptr, pR, pWlT, out, blin, NNODES, 256, 256);
}

// round 17
// speedup vs baseline: 1.4529x; 1.0316x over previous
#include <cuda_runtime.h>
#include <cuda_fp16.h>
#include <stdint.h>
#include <math.h>

// ---------------------------------------------------------------------------
// GCLSTM (K=1 ChebConv -> edge data unused). fp16 HMMA path.
//   pack(Wt,bias) -> GEMM1 -> gates -> GEMM2      [default stream]
//   pack(WlinT)  || GEMM1                          [side stream]
//   GEMM1: P(fp16) = [x|h](fp32, cvt in-loader) @ Wt^T + bias,
//          *** fp16-accumulate HMMA *** (P is fp16 anyway)  (50000x1024x512)
//   gates: h0, c0 (fp32), R = relu(h0) (fp16)
//   GEMM2: out = R @ WlinT^T + b_lin, fp32-accumulate     (50000x256x256)
// GEMM: BM=128, BN=256, BK=32, 8 warps (2m x 4n), warp 64x64, 4-stage.
// Output tuple: [out | h0 | c0], each 50000*256 fp32.
// ---------------------------------------------------------------------------

#define NNODES 50000

__device__ __half g_P[(size_t)NNODES * 1024];
__device__ __half g_R[(size_t)NNODES * 256];
__device__ __half g_Wt[1024 * 512];
__device__ __half g_WlT[256 * 256];
__device__ float  g_bias[1024];

// ---------------------------------------------------------------------------
__device__ __forceinline__ uint32_t smem_u32(const void* p) {
    uint32_t a;
    asm("{ .reg .u64 t; cvta.to.shared.u64 t, %1; cvt.u32.u64 %0, t; }"
        : "=r"(a) : "l"(p));
    return a;
}
__device__ __forceinline__ void ldm4(uint32_t* a, uint32_t addr) {
    asm volatile("ldmatrix.sync.aligned.m8n8.x4.shared.b16 {%0,%1,%2,%3}, [%4];"
        : "=r"(a[0]), "=r"(a[1]), "=r"(a[2]), "=r"(a[3]) : "r"(addr));
}
__device__ __forceinline__ void mma_f32(float* d, const uint32_t* a, const uint32_t* b) {
    asm volatile(
        "mma.sync.aligned.m16n8k16.row.col.f32.f16.f16.f32 "
        "{%0,%1,%2,%3},{%4,%5,%6,%7},{%8,%9},{%0,%1,%2,%3};"
        : "+f"(d[0]), "+f"(d[1]), "+f"(d[2]), "+f"(d[3])
        : "r"(a[0]), "r"(a[1]), "r"(a[2]), "r"(a[3]), "r"(b[0]), "r"(b[1]));
}
__device__ __forceinline__ void mma_f16(uint32_t* d, const uint32_t* a, const uint32_t* b) {
    asm volatile(
        "mma.sync.aligned.m16n8k16.row.col.f16.f16.f16.f16 "
        "{%0,%1},{%2,%3,%4,%5},{%6,%7},{%0,%1};"
        : "+r"(d[0]), "+r"(d[1])
        : "r"(a[0]), "r"(a[1]), "r"(a[2]), "r"(a[3]), "r"(b[0]), "r"(b[1]));
}
__device__ __forceinline__ void cp16(uint32_t dst, const void* src) {
    asm volatile("cp.async.cg.shared.global [%0], [%1], 16;" :: "r"(dst), "l"(src));
}
__device__ __forceinline__ void cp_commit() { asm volatile("cp.async.commit_group;"); }
template <int N>
__device__ __forceinline__ void cp_wait() {
    asm volatile("cp.async.wait_group %0;" :: "n"(N));
}

__device__ __forceinline__ float sigf(float x)  { return 1.f / (1.f + __expf(-x)); }
__device__ __forceinline__ float tanf_(float x) { return 2.f / (1.f + __expf(-2.f * x)) - 1.f; }

// ---------------------------------------------------------------------------
// Common tile/pipeline constants: BM=128, BN=256, BK=32, 4-stage.
// ---------------------------------------------------------------------------
#define ABUF (128 * 80)
#define BBUF (256 * 80)
#define STG  (ABUF + BBUF)
#define SMEM_DYN (4 * STG)           // 122880 B

// ---------------------------------------------------------------------------
// GEMM1: fp16-accumulate. A = [x|h] fp32 LDG->cvt->STS; B fp16 cp.async.
// P(fp16) = A @ B^T + bias.
// ---------------------------------------------------------------------------
__global__ void __launch_bounds__(256, 1)
gemm1_kernel(const float* __restrict__ Ax, const float* __restrict__ Ah,
             const __half* __restrict__ B, __half* __restrict__ C,
             const float* __restrict__ bias, int M)
{
    extern __shared__ __align__(16) char usm[];
    __shared__ float sbias[256];

    const int tid  = threadIdx.x;
    const int lane = tid & 31;
    const int wid  = tid >> 5;
    const int warpm = wid >> 2;
    const int warpn = wid & 3;
    const int m0 = blockIdx.y * 128;
    const int n0 = blockIdx.x * 256;
    const int K = 512, Ntot = 1024;

    const uint32_t smb = smem_u32(usm);
    sbias[tid] = bias[n0 + tid];

    uint32_t acc[4][8][2];               // fp16x2 accumulators
#pragma unroll
    for (int mt = 0; mt < 4; ++mt)
#pragma unroll
        for (int nt = 0; nt < 8; ++nt) {
            acc[mt][nt][0] = 0u;
            acc[mt][nt][1] = 0u;
        }

    float4 areg[4];
    const int a_r  = tid >> 3;
    const int a_fq = tid & 7;

    auto fetchA32 = [&](int kc) {
        const float* src = (kc < 8) ? Ax : Ah;
        const int cb = (kc & 7) * 32;
#pragma unroll
        for (int q = 0; q < 4; ++q) {
            int r = a_r + q * 32;
            int gr = m0 + r;
            areg[q] = make_float4(0.f, 0.f, 0.f, 0.f);
            if (gr < M)
                areg[q] = *(const float4*)(src + (size_t)gr * 256 + cb + a_fq * 4);
        }
    };
    auto storeA32 = [&](int st) {
#pragma unroll
        for (int q = 0; q < 4; ++q) {
            int r = a_r + q * 32;
            __half2 h0 = __floats2half2_rn(areg[q].x, areg[q].y);
            __half2 h1 = __floats2half2_rn(areg[q].z, areg[q].w);
            uint2 v;
            v.x = *(uint32_t*)&h0;
            v.y = *(uint32_t*)&h1;
            *(uint2*)(usm + st * STG + r * 80 + a_fq * 8) = v;
        }
    };
    auto issueB = [&](int kc, int st) {
        const uint32_t bb = smb + st * STG + ABUF;
#pragma unroll
        for (int q = 0; q < 4; ++q) {
            int u = tid + q * 256;
            int r = u >> 2, kq = u & 3;
            cp16(bb + r * 80 + kq * 16,
                 B + (size_t)(n0 + r) * K + kc * 32 + kq * 8);
        }
    };

    fetchA32(0); storeA32(0);
    fetchA32(1); storeA32(1);
    fetchA32(2); storeA32(2);
    issueB(0, 0); cp_commit();
    issueB(1, 1); cp_commit();
    issueB(2, 2); cp_commit();
    cp_wait<2>();
    __syncthreads();

    const int arow = warpm * 64 + (lane & 15);
    const int aoff = (lane >> 4) * 8;
    const int brow = warpn * 64 + ((lane >> 4) << 3) + (lane & 7);
    const int boff = ((lane >> 3) & 1) * 8;

    const int nch = K >> 5;
    for (int t = 0; t < nch; ++t) {
        const bool pf = (t + 3 < nch);
        if (pf) {
            fetchA32(t + 3);
            issueB(t + 3, (t + 3) & 3);
        }
        cp_commit();

        const int st = t & 3;
        const uint32_t ab = smb + st * STG + arow * 80;
        const uint32_t bb = smb + st * STG + ABUF + brow * 80;
#pragma unroll
        for (int ks = 0; ks < 2; ++ks) {
            const int k0 = ks * 16;
            uint32_t afr[4][4], bfr[8][2];
#pragma unroll
            for (int mt = 0; mt < 4; ++mt)
                ldm4(afr[mt], ab + mt * 16 * 80 + (k0 + aoff) * 2);
#pragma unroll
            for (int np = 0; np < 4; ++np) {
                uint32_t f[4];
                ldm4(f, bb + np * 16 * 80 + (k0 + boff) * 2);
                bfr[np * 2][0] = f[0]; bfr[np * 2][1] = f[1];
                bfr[np * 2 + 1][0] = f[2]; bfr[np * 2 + 1][1] = f[3];
            }
#pragma unroll
            for (int mt = 0; mt < 4; ++mt)
#pragma unroll
                for (int nt = 0; nt < 8; ++nt)
                    mma_f16(acc[mt][nt], afr[mt], bfr[nt]);
        }

        if (pf) storeA32((t + 3) & 3);
        cp_wait<2>();
        __syncthreads();
    }

    // ---- epilogue: unpack fp16 acc, add fp32 bias, store fp16 P ----
#pragma unroll
    for (int mt = 0; mt < 4; ++mt) {
        int r0 = m0 + warpm * 64 + mt * 16 + (lane >> 2);
        int r1 = r0 + 8;
#pragma unroll
        for (int nt = 0; nt < 8; ++nt) {
            int cl = warpn * 64 + nt * 8 + (lane & 3) * 2;
            int cg = n0 + cl;
            float b0 = sbias[cl], b1 = sbias[cl + 1];
            float2 f0 = __half22float2(*(__half2*)&acc[mt][nt][0]);
            float2 f1 = __half22float2(*(__half2*)&acc[mt][nt][1]);
            if (r0 < M)
                *(__half2*)(C + (size_t)r0 * Ntot + cg) =
                    __floats2half2_rn(f0.x + b0, f0.y + b1);
            if (r1 < M)
                *(__half2*)(C + (size_t)r1 * Ntot + cg) =
                    __floats2half2_rn(f1.x + b0, f1.y + b1);
        }
    }
}

// ---------------------------------------------------------------------------
// GEMM2: fp32-accumulate (unchanged, best measured). A fp16 via cp.async.
// out(fp32) = R @ WlinT^T + b_lin.
// ---------------------------------------------------------------------------
__global__ void __launch_bounds__(256, 1)
gemm2_kernel(const __half* __restrict__ A16, const __half* __restrict__ B,
             float* __restrict__ C, const float* __restrict__ bias, int M)
{
    extern __shared__ __align__(16) char usm[];
    __shared__ float sbias[256];

    const int tid  = threadIdx.x;
    const int lane = tid & 31;
    const int wid  = tid >> 5;
    const int warpm = wid >> 2;
    const int warpn = wid & 3;
    const int m0 = blockIdx.y * 128;
    const int n0 = blockIdx.x * 256;
    const int K = 256, Ntot = 256;

    const uint32_t smb = smem_u32(usm);
    sbias[tid] = bias[n0 + tid];

    float acc[4][8][4];
#pragma unroll
    for (int mt = 0; mt < 4; ++mt)
#pragma unroll
        for (int nt = 0; nt < 8; ++nt)
#pragma unroll
            for (int e = 0; e < 4; ++e) acc[mt][nt][e] = 0.f;

    auto issueA16 = [&](int kc, int st) {
#pragma unroll
        for (int q = 0; q < 2; ++q) {
            int u = tid + q * 256;
            int r = u >> 2, kq = u & 3;
            int gr = m0 + r;
            if (gr < M)
                cp16(smb + st * STG + r * 80 + kq * 16,
                     A16 + (size_t)gr * K + kc * 32 + kq * 8);
        }
    };
    auto issueB = [&](int kc, int st) {
        const uint32_t bb = smb + st * STG + ABUF;
#pragma unroll
        for (int q = 0; q < 4; ++q) {
            int u = tid + q * 256;
            int r = u >> 2, kq = u & 3;
            cp16(bb + r * 80 + kq * 16,
                 B + (size_t)(n0 + r) * K + kc * 32 + kq * 8);
        }
    };

    issueA16(0, 0); issueB(0, 0); cp_commit();
    issueA16(1, 1); issueB(1, 1); cp_commit();
    issueA16(2, 2); issueB(2, 2); cp_commit();
    cp_wait<2>();
    __syncthreads();

    const int arow = warpm * 64 + (lane & 15);
    const int aoff = (lane >> 4) * 8;
    const int brow = warpn * 64 + ((lane >> 4) << 3) + (lane & 7);
    const int boff = ((lane >> 3) & 1) * 8;

    const int nch = K >> 5;
    for (int t = 0; t < nch; ++t) {
        const bool pf = (t + 3 < nch);
        if (pf) {
            issueA16(t + 3, (t + 3) & 3);
            issueB(t + 3, (t + 3) & 3);
        }
        cp_commit();

        const int st = t & 3;
        const uint32_t ab = smb + st * STG + arow * 80;
        const uint32_t bb = smb + st * STG + ABUF + brow * 80;
#pragma unroll
        for (int ks = 0; ks < 2; ++ks) {
            const int k0 = ks * 16;
            uint32_t afr[4][4], bfr[8][2];
#pragma unroll
            for (int mt = 0; mt < 4; ++mt)
                ldm4(afr[mt], ab + mt * 16 * 80 + (k0 + aoff) * 2);
#pragma unroll
            for (int np = 0; np < 4; ++np) {
                uint32_t f[4];
                ldm4(f, bb + np * 16 * 80 + (k0 + boff) * 2);
                bfr[np * 2][0] = f[0]; bfr[np * 2][1] = f[1];
                bfr[np * 2 + 1][0] = f[2]; bfr[np * 2 + 1][1] = f[3];
            }
#pragma unroll
            for (int mt = 0; mt < 4; ++mt)
#pragma unroll
                for (int nt = 0; nt < 8; ++nt)
                    mma_f32(acc[mt][nt], afr[mt], bfr[nt]);
        }

        cp_wait<2>();
        __syncthreads();
    }

#pragma unroll
    for (int mt = 0; mt < 4; ++mt) {
        int r0 = m0 + warpm * 64 + mt * 16 + (lane >> 2);
        int r1 = r0 + 8;
#pragma unroll
        for (int nt = 0; nt < 8; ++nt) {
            int cl = warpn * 64 + nt * 8 + (lane & 3) * 2;
            int cg = n0 + cl;
            float b0 = sbias[cl], b1 = sbias[cl + 1];
            if (r0 < M)
                *(float2*)(C + (size_t)r0 * Ntot + cg) =
                    make_float2(acc[mt][nt][0] + b0, acc[mt][nt][1] + b1);
            if (r1 < M)
                *(float2*)(C + (size_t)r1 * Ntot + cg) =
                    make_float2(acc[mt][nt][2] + b0, acc[mt][nt][3] + b1);
        }
    }
}

// ---------------------------------------------------------------------------
__global__ void pack_main(
    const float* __restrict__ Wi, const float* __restrict__ Wf,
    const float* __restrict__ Wc, const float* __restrict__ Wo,
    const float* __restrict__ Ti, const float* __restrict__ Tf,
    const float* __restrict__ Tc, const float* __restrict__ To,
    const float* __restrict__ bthi, const float* __restrict__ bthf,
    const float* __restrict__ bthc, const float* __restrict__ btho,
    const float* __restrict__ bi, const float* __restrict__ bf,
    const float* __restrict__ bc, const float* __restrict__ bo)
{
    int idx = blockIdx.x * blockDim.x + threadIdx.x;
    if (idx < 524288) {
        int n = idx >> 9, k = idx & 511;
        int g = n >> 8, jj = n & 255;
        float v;
        if (k < 256) {
            const float* W = (g == 0) ? Wi : (g == 1) ? Wf : (g == 2) ? Wc : Wo;
            v = W[k * 256 + jj];
        } else {
            const float* T = (g == 0) ? Ti : (g == 1) ? Tf : (g == 2) ? Tc : To;
            v = T[(k - 256) * 256 + jj];
        }
        g_Wt[idx] = __float2half_rn(v);
    } else if (idx < 524288 + 1024) {
        int j = idx - 524288;
        int g = j >> 8, jj = j & 255;
        const float* bth = (g == 0) ? bthi : (g == 1) ? bthf : (g == 2) ? bthc : btho;
        const float* bb  = (g == 0) ? bi   : (g == 1) ? bf   : (g == 2) ? bc   : bo;
        g_bias[j] = bth[jj] + bb[jj];
    }
}

__global__ void pack_wlin(const float* __restrict__ Wlin)
{
    int idx = blockIdx.x * blockDim.x + threadIdx.x;
    if (idx < 65536) {
        int n = idx >> 8, k = idx & 255;
        g_WlT[idx] = __float2half_rn(Wlin[k * 256 + n]);
    }
}

// ---------------------------------------------------------------------------
__global__ void gates_kernel(const float* __restrict__ c_in,
                             const float* __restrict__ wci,
                             const float* __restrict__ wcf,
                             const float* __restrict__ wco,
                             float* __restrict__ h_out,
                             float* __restrict__ c_out)
{
    int u = blockIdx.x * blockDim.x + threadIdx.x;   // NNODES*32
    if (u >= NNODES * 32) return;
    int n = u >> 5;
    int j = (u & 31) << 3;
    const __half* P = g_P + (size_t)n * 1024;

    uint4 vi = *(const uint4*)(P + j);
    uint4 vf = *(const uint4*)(P + 256 + j);
    uint4 vc = *(const uint4*)(P + 512 + j);
    uint4 vo = *(const uint4*)(P + 768 + j);
    float4 c0 = *(const float4*)(c_in + (size_t)n * 256 + j);
    float4 c1 = *(const float4*)(c_in + (size_t)n * 256 + j + 4);
    float4 wi0 = *(const float4*)(wci + j), wi1 = *(const float4*)(wci + j + 4);
    float4 wf0 = *(const float4*)(wcf + j), wf1 = *(const float4*)(wcf + j + 4);
    float4 wo0 = *(const float4*)(wco + j), wo1 = *(const float4*)(wco + j + 4);

    float pi[8], pf[8], pc[8], po[8];
    {
        const uint32_t* a = &vi.x;
        const uint32_t* b = &vf.x;
        const uint32_t* cc = &vc.x;
        const uint32_t* d = &vo.x;
#pragma unroll
        for (int q = 0; q < 4; ++q) {
            float2 t;
            t = __half22float2(*(const __half2*)&a[q]);  pi[2*q] = t.x; pi[2*q+1] = t.y;
            t = __half22float2(*(const __half2*)&b[q]);  pf[2*q] = t.x; pf[2*q+1] = t.y;
            t = __half22float2(*(const __half2*)&cc[q]); pc[2*q] = t.x; pc[2*q+1] = t.y;
            t = __half22float2(*(const __half2*)&d[q]);  po[2*q] = t.x; po[2*q+1] = t.y;
        }
    }
    float cv[8]  = {c0.x, c0.y, c0.z, c0.w, c1.x, c1.y, c1.z, c1.w};
    float wia[8] = {wi0.x, wi0.y, wi0.z, wi0.w, wi1.x, wi1.y, wi1.z, wi1.w};
    float wfa[8] = {wf0.x, wf0.y, wf0.z, wf0.w, wf1.x, wf1.y, wf1.z, wf1.w};
    float woa[8] = {wo0.x, wo0.y, wo0.z, wo0.w, wo1.x, wo1.y, wo1.z, wo1.w};

    float H[8], Cn[8];
#pragma unroll
    for (int e = 0; e < 8; ++e) {
        float I = sigf(pi[e] + wia[e] * cv[e]);
        float F = sigf(pf[e] + wfa[e] * cv[e]);
        float T = tanf_(pc[e]);
        Cn[e] = F * cv[e] + I * T;
        float O = sigf(po[e] + woa[e] * Cn[e]);
        H[e] = O * tanf_(Cn[e]);
    }

    size_t off = (size_t)n * 256 + j;
    *(float4*)(h_out + off)     = make_float4(H[0], H[1], H[2], H[3]);
    *(float4*)(h_out + off + 4) = make_float4(H[4], H[5], H[6], H[7]);
    *(float4*)(c_out + off)     = make_float4(Cn[0], Cn[1], Cn[2], Cn[3]);
    *(float4*)(c_out + off + 4) = make_float4(Cn[4], Cn[5], Cn[6], Cn[7]);

    uint4 rv;
    __half2 r01 = __floats2half2_rn(fmaxf(H[0], 0.f), fmaxf(H[1], 0.f));
    __half2 r23 = __floats2half2_rn(fmaxf(H[2], 0.f), fmaxf(H[3], 0.f));
    __half2 r45 = __floats2half2_rn(fmaxf(H[4], 0.f), fmaxf(H[5], 0.f));
    __half2 r67 = __floats2half2_rn(fmaxf(H[6], 0.f), fmaxf(H[7], 0.f));
    rv.x = *(uint32_t*)&r01; rv.y = *(uint32_t*)&r23;
    rv.z = *(uint32_t*)&r45; rv.w = *(uint32_t*)&r67;
    *(uint4*)(g_R + off) = rv;
}

// ---------------------------------------------------------------------------
extern "C" void kernel_launch(void* const* d_in, const int* in_sizes, int n_in,
                              void* d_out, int out_size)
{
    const float* x    = (const float*)d_in[0];
    // d_in[1] edge_index, d_in[2] edge_weight -> unused (K=1 ChebConv)
    const float* h    = (const float*)d_in[3];
    const float* c    = (const float*)d_in[4];
    const float* Wi   = (const float*)d_in[5];
    const float* Wf   = (const float*)d_in[6];
    const float* Wc   = (const float*)d_in[7];
    const float* Wo   = (const float*)d_in[8];
    const float* Ti   = (const float*)d_in[9];
    const float* Tf   = (const float*)d_in[10];
    const float* Tc   = (const float*)d_in[11];
    const float* To   = (const float*)d_in[12];
    const float* bthi = (const float*)d_in[13];
    const float* bthf = (const float*)d_in[14];
    const float* bthc = (const float*)d_in[15];
    const float* btho = (const float*)d_in[16];
    const float* wci  = (const float*)d_in[17];
    const float* wcf  = (const float*)d_in[18];
    const float* wco  = (const float*)d_in[19];
    const float* bi   = (const float*)d_in[20];
    const float* bf   = (const float*)d_in[21];
    const float* bc   = (const float*)d_in[22];
    const float* bo   = (const float*)d_in[23];
    const float* Wlin = (const float*)d_in[24];
    const float* blin = (const float*)d_in[25];
    float* out = (float*)d_out;

    float *pBias;
    __half *pP, *pWt, *pWlT, *pR;
    cudaGetSymbolAddress((void**)&pBias, g_bias);
    cudaGetSymbolAddress((void**)&pP, g_P);
    cudaGetSymbolAddress((void**)&pWt, g_Wt);
    cudaGetSymbolAddress((void**)&pWlT, g_WlT);
    cudaGetSymbolAddress((void**)&pR, g_R);

    cudaFuncSetAttribute(gemm1_kernel,
                         cudaFuncAttributeMaxDynamicSharedMemorySize, SMEM_DYN);
    cudaFuncSetAttribute(gemm2_kernel,
                         cudaFuncAttributeMaxDynamicSharedMemorySize, SMEM_DYN);

    // one-time host-side stream/event setup (no device memory)
    static cudaStream_t s2 = nullptr;
    static cudaEvent_t evFork, evWlin;
    if (!s2) {
        cudaStreamCreateWithFlags(&s2, cudaStreamNonBlocking);
        cudaEventCreateWithFlags(&evFork, cudaEventDisableTiming);
        cudaEventCreateWithFlags(&evWlin, cudaEventDisableTiming);
    }

    const size_t elems = (size_t)NNODES * 256;
    float* hout = out + elems;
    float* cout = out + 2 * elems;

    // pack Wt+bias (default; GEMM1 depends on it)
    pack_main<<<(524288 + 1024 + 255) / 256, 256>>>(
        Wi, Wf, Wc, Wo, Ti, Tf, Tc, To,
        bthi, bthf, bthc, btho, bi, bf, bc, bo);

    // pack WlinT on side stream (overlaps GEMM1; only GEMM2 needs it)
    cudaEventRecord(evFork, 0);
    cudaStreamWaitEvent(s2, evFork, 0);
    pack_wlin<<<65536 / 256, 256, 0, s2>>>(Wlin);
    cudaEventRecord(evWlin, s2);

    // GEMM1: P = [x|h] @ Wt^T + bias  (fp16 accumulate)
    gemm1_kernel<<<dim3(4, (NNODES + 127) / 128), 256, SMEM_DYN>>>(
        x, h, pWt, pP, pBias, NNODES);

    // gates -> h0, c0, R
    gates_kernel<<<(NNODES * 32 + 255) / 256, 256>>>(
        c, wci, wcf, wco, hout, cout);

    // GEMM2: out = R @ WlinT^T + b_lin  (fp32 accumulate)
    cudaStreamWaitEvent(0, evWlin, 0);
    gemm2_kernel<<<dim3(1, (NNODES + 127) / 128), 256, SMEM_DYN>>>(
        pR, pWlT, out, blin, NNODES);
}